// round 8
// baseline (speedup 1.0000x reference)
#include <cuda_runtime.h>
#include <cuda_bf16.h>
#include <math.h>
#include <stdint.h>

// Problem constants
#define Bsz 2
#define Npt 4096
#define CP 128
#define CI 256
#define DM 128
#define NH 4
#define KS 8
#define HF 64
#define WF 128
#define DH 32
#define NPTS (Bsz*Npt)      // 8192
#define HW (HF*WF)          // 8192

// ---------------- scratch (device globals; no allocation allowed) -------------
__device__ float g_img_t[Bsz*HW*CI];        // [B][HW][CI]
__device__ float g_Qp[NPTS*DM];
__device__ float g_Fagg[NPTS*CI];
__device__ float g_q[NPTS*DM];
__device__ float g_kv[NPTS*2*DM];           // [p][0:128]=k, [p][128:256]=v
__device__ float g_o[NPTS*DM];
__device__ float g_concat[NPTS*(CP+DM)];
__device__ float g_h[NPTS*DM];
__device__ float g_wkv[2*DM*CI];
__device__ float g_bkv[2*DM];
__device__ float g_offlog[NPTS*24];

// ---------------- tf32 mma helper ---------------------------------------------
__device__ __forceinline__ void mma_tf32(float* d, const uint32_t* a, const uint32_t* b) {
    asm volatile(
        "mma.sync.aligned.m16n8k8.row.col.f32.tf32.tf32.f32 "
        "{%0,%1,%2,%3}, {%4,%5,%6,%7}, {%8,%9}, {%0,%1,%2,%3};\n"
        : "+f"(d[0]), "+f"(d[1]), "+f"(d[2]), "+f"(d[3])
        : "r"(a[0]), "r"(a[1]), "r"(a[2]), "r"(a[3]), "r"(b[0]), "r"(b[1]));
}

// ---------------- img_feat transpose ------------------------------------------
__global__ void transpose_img(const float* __restrict__ in) {
    __shared__ float tile[32][33];
    int b  = blockIdx.z;
    int hw0 = blockIdx.x * 32;
    int c0  = blockIdx.y * 32;
    int tx = threadIdx.x, ty = threadIdx.y;
#pragma unroll
    for (int i = 0; i < 4; i++) {
        int c = c0 + ty + i * 8;
        tile[ty + i * 8][tx] = in[((long)(b * CI + c)) * HW + hw0 + tx];
    }
    __syncthreads();
#pragma unroll
    for (int i = 0; i < 4; i++) {
        int hw = hw0 + ty + i * 8;
        g_img_t[((long)b * HW + hw) * CI + c0 + tx] = tile[tx][ty + i * 8];
    }
}

// ---------------- fuse K/V projection weights ---------------------------------
__global__ void fuse_weights(const float* __restrict__ in_wk, const float* __restrict__ w_k,
                             const float* __restrict__ b_k, const float* __restrict__ in_bk,
                             const float* __restrict__ in_wv, const float* __restrict__ w_v,
                             const float* __restrict__ b_v, const float* __restrict__ in_bv) {
    int i = blockIdx.x;
    int sel = blockIdx.y;
    int j = threadIdx.x;
    const float* inw = sel ? in_wv : in_wk;
    const float* w   = sel ? w_v : w_k;
    float acc = 0.f;
#pragma unroll 8
    for (int d = 0; d < DM; d++) acc += inw[i * DM + d] * w[d * CI + j];
    g_wkv[(sel * DM + i) * CI + j] = acc;
    if (j == 0) {
        const float* bb  = sel ? b_v : b_k;
        const float* inb = sel ? in_bv : in_bk;
        float ba = 0.f;
        for (int d = 0; d < DM; d++) ba += inw[i * DM + d] * bb[d];
        g_bkv[sel * DM + i] = ba + inb[i];
    }
}

// ---------------- tf32 MMA GEMM: C = A @ W^T + bias, 128x64 tile --------------
// 256 thr = 8 warps. Warp w: rows (w&3)*32 (2 m16 subtiles), cols (w>>2)*32.
__global__ __launch_bounds__(256) void gemm128t(const float* __restrict__ A,
                                                const float* __restrict__ W,
                                                const float* __restrict__ bias,
                                                float* __restrict__ C,
                                                int K, int ldc, int c0) {
    __shared__ float As[128][36];
    __shared__ float Ws[64][36];
    int tid = threadIdx.x;
    int lane = tid & 31, w = tid >> 5;
    int m0b = blockIdx.x * 128, n0b = blockIdx.y * 64;
    int ra = tid >> 1, da = (tid & 1) * 16;     // A loads: 128 rows x 32
    int rw = tid >> 2, dw = (tid & 3) * 8;      // W loads: 64 rows x 32
    int mm = (w & 3) * 32, nh = w >> 2;
    int g = lane >> 2, c4 = lane & 3;
    float acc[2][4][4] = {};
    for (int k0 = 0; k0 < K; k0 += 32) {
        const float4* as = (const float4*)&A[(long)(m0b + ra) * K + k0 + da];
        *(float4*)&As[ra][da]      = as[0];
        *(float4*)&As[ra][da + 4]  = as[1];
        *(float4*)&As[ra][da + 8]  = as[2];
        *(float4*)&As[ra][da + 12] = as[3];
        const float4* ws = (const float4*)&W[(long)(n0b + rw) * K + k0 + dw];
        *(float4*)&Ws[rw][dw]     = ws[0];
        *(float4*)&Ws[rw][dw + 4] = ws[1];
        __syncthreads();
#pragma unroll
        for (int ks = 0; ks < 4; ks++) {
            uint32_t bf[4][2];
#pragma unroll
            for (int nt = 0; nt < 4; nt++) {
                int n0 = nh * 32 + nt * 8;
                bf[nt][0] = __float_as_uint(Ws[n0 + g][ks * 8 + c4]);
                bf[nt][1] = __float_as_uint(Ws[n0 + g][ks * 8 + c4 + 4]);
            }
#pragma unroll
            for (int mt = 0; mt < 2; mt++) {
                int mb = mm + mt * 16;
                uint32_t a[4];
                a[0] = __float_as_uint(As[mb + g][ks * 8 + c4]);
                a[1] = __float_as_uint(As[mb + 8 + g][ks * 8 + c4]);
                a[2] = __float_as_uint(As[mb + g][ks * 8 + c4 + 4]);
                a[3] = __float_as_uint(As[mb + 8 + g][ks * 8 + c4 + 4]);
#pragma unroll
                for (int nt = 0; nt < 4; nt++) mma_tf32(acc[mt][nt], a, bf[nt]);
            }
        }
        __syncthreads();
    }
#pragma unroll
    for (int mt = 0; mt < 2; mt++)
#pragma unroll
        for (int nt = 0; nt < 4; nt++) {
            int n = n0b + nh * 32 + nt * 8 + 2 * c4;
            float b0 = bias[n], b1 = bias[n + 1];
            long row0 = m0b + mm + mt * 16 + g, row1 = row0 + 8;
            *(float2*)&C[row0 * ldc + c0 + n] = make_float2(acc[mt][nt][0] + b0, acc[mt][nt][1] + b1);
            *(float2*)&C[row1 * ldc + c0 + n] = make_float2(acc[mt][nt][2] + b0, acc[mt][nt][3] + b1);
        }
}

// ---------------- offlog ------------------------------------------------------
__global__ __launch_bounds__(256) void offlog_kernel(const float* __restrict__ w_off,
                                                     const float* __restrict__ b_off,
                                                     const float* __restrict__ w_alpha,
                                                     const float* __restrict__ b_alpha) {
    __shared__ float wsm[24][128];
    __shared__ float bsm[24];
    int tid = threadIdx.x;
    for (int idx = tid; idx < 24 * 128; idx += 256) {
        int row = idx >> 7, col = idx & 127;
        wsm[row][col] = (row < 16) ? w_off[row * DM + col] : w_alpha[(row - 16) * DM + col];
    }
    if (tid < 24) bsm[tid] = (tid < 16) ? b_off[tid] : b_alpha[tid - 16];
    __syncthreads();
    int lane = tid & 31, w = tid >> 5;
    long p = (long)blockIdx.x * 8 + w;
    float q0 = g_Qp[p * DM + lane];
    float q1 = g_Qp[p * DM + lane + 32];
    float q2 = g_Qp[p * DM + lane + 64];
    float q3 = g_Qp[p * DM + lane + 96];
#pragma unroll
    for (int o = 0; o < 24; o++) {
        float s = q0 * wsm[o][lane] + q1 * wsm[o][lane + 32]
                + q2 * wsm[o][lane + 64] + q3 * wsm[o][lane + 96];
#pragma unroll
        for (int off = 16; off; off >>= 1) s += __shfl_xor_sync(0xffffffffu, s, off);
        if (lane == 0) g_offlog[p * 24 + o] = s + bsm[o];
    }
}

// ---------------- sampler: warp-per-point deformable gather -------------------
__global__ __launch_bounds__(256) void sampler_kernel(
        const float* __restrict__ xyz, const float* __restrict__ feat_pc,
        const float* __restrict__ Km, const float* __restrict__ Tc,
        const float* __restrict__ img_size) {
    int tid = threadIdx.x;
    int lane = tid & 31, w = tid >> 5;
    long p = (long)blockIdx.x * 8 + w;
    int b = (int)(p >> 12);

#pragma unroll
    for (int j = 0; j < 4; j++)
        g_concat[p * (CP + DM) + j * 32 + lane] = feat_pc[p * CP + j * 32 + lane];

    float ol = (lane < 24) ? g_offlog[p * 24 + lane] : 0.f;

    float lg = __shfl_sync(0xffffffffu, ol, 16 + (lane & 7));
    float mx = lg;
#pragma unroll
    for (int o = 1; o <= 4; o <<= 1) mx = fmaxf(mx, __shfl_xor_sync(0xffffffffu, mx, o));
    float ex = __expf(lg - mx);
    float se = ex;
#pragma unroll
    for (int o = 1; o <= 4; o <<= 1) se += __shfl_xor_sync(0xffffffffu, se, o);

    int k = lane >> 2, c = lane & 3;
    float al = __shfl_sync(0xffffffffu, ex, k) / se;
    float offu = __shfl_sync(0xffffffffu, ol, 2 * k);
    float offv = __shfl_sync(0xffffffffu, ol, 2 * k + 1);

    float X = xyz[p * 3], Y = xyz[p * 3 + 1], Z = xyz[p * 3 + 2];
    const float* T = Tc + b * 16;
    float Xc = T[0] * X + T[1] * Y + T[2]  * Z + T[3];
    float Yc = T[4] * X + T[5] * Y + T[6]  * Z + T[7];
    float Zc = T[8] * X + T[9] * Y + T[10] * Z + T[11];
    float Zf = -Zc;
    float Zs = (Zf > 1e-6f) ? Zf : 1e-6f;
    const float* Kc = Km + b * 9;
    float u = (Kc[0] * Xc + Kc[1] * Yc + Kc[2] * Zf) / Zs;
    float v = (Kc[3] * Xc + Kc[4] * Yc + Kc[5] * Zf) / Zs;
    float Hi = img_size[b * 2], Wi = img_size[b * 2 + 1];
    float Hfi = fmaxf(Hi / 8.f, 1.f), Wfi = fmaxf(Wi / 8.f, 1.f);
    float uf = u * (Wfi / Wi), vf = v * (Hfi / Hi);

    float us = uf + offu, vs = vf + offv;
    float xn = fminf(fmaxf(2.f * (us / 127.f) - 1.f, -1.5f), 1.5f);
    float yn = fminf(fmaxf(2.f * (vs / 63.f)  - 1.f, -1.5f), 1.5f);
    float ix = ((xn + 1.f) * (float)WF - 1.f) * 0.5f;
    float iy = ((yn + 1.f) * (float)HF - 1.f) * 0.5f;
    float x0f = floorf(ix), y0f = floorf(iy);
    float wx1 = ix - x0f, wx0 = 1.f - wx1;
    float wy1 = iy - y0f, wy0 = 1.f - wy1;
    float xc = x0f + (float)(c & 1);
    float yc = y0f + (float)(c >> 1);
    float wgt = ((c & 1) ? wx1 : wx0) * ((c >> 1) ? wy1 : wy0) * al;
    bool valid = (xc >= 0.f) && (xc < (float)WF) && (yc >= 0.f) && (yc < (float)HF);
    int xi = min(max((int)xc, 0), WF - 1);
    int yi = min(max((int)yc, 0), HF - 1);
    int sidx = yi * WF + xi;
    if (!valid) wgt = 0.f;

    float acc[8] = {};
    const float* imgb = g_img_t + (long)b * HW * CI + lane;
#pragma unroll
    for (int e = 0; e < 32; e++) {
        float we = __shfl_sync(0xffffffffu, wgt, e);
        int   ie = __shfl_sync(0xffffffffu, sidx, e);
        if (we != 0.f) {
            const float* basep = imgb + (long)ie * CI;
#pragma unroll
            for (int j = 0; j < 8; j++) acc[j] += we * basep[j * 32];
        }
    }
#pragma unroll
    for (int j = 0; j < 8; j++) g_Fagg[p * CI + j * 32 + lane] = acc[j];
}

// ---------------- flash attention v2 (R5-passing): BQ=64, static smem ---------
// 256 thr = 8 warps. Warp w: rows mm=(w&3)*16; col-half nh=w>>2.
__global__ __launch_bounds__(256) void flash_attn_mma(const float* __restrict__ Q,
                                                      const float* __restrict__ KV,
                                                      float* __restrict__ O) {
    __shared__ float Ks[64][36];
    __shared__ float Vt[32][68];        // [dim][key]
    __shared__ float Ps[64][68];        // P tile; also stages Q in prologue
    __shared__ float pm[64][2];
    __shared__ float psum[64][2];

    int tid = threadIdx.x;
    int lane = tid & 31, w = tid >> 5;
    int bh = blockIdx.y;
    int b = bh >> 2, h = bh & 3;
    int q0 = blockIdx.x * 64;

    int r = tid >> 2, dd = (tid & 3) * 8;
    int mm = (w & 3) * 16, nh = w >> 2;
    int g = lane >> 2, c4 = lane & 3;
    int r0 = mm + g, r1 = mm + 8 + g;

    {   // prologue: stage Q into Ps area, K0/V0 into Ks/Vt
        const float4* src = (const float4*)(Q + ((long)(b * Npt + q0 + r)) * DM + h * DH + dd);
        *(float4*)&Ps[r][dd]     = src[0];
        long rowbase = ((long)(b * Npt + r)) * (2 * DM) + h * DH + dd;
        const float4* ksrc = (const float4*)(KV + rowbase);
        *(float4*)&Ks[r][dd]     = ksrc[0];
        *(float4*)&Ks[r][dd + 4] = ksrc[1];
        const float4* vsrc = (const float4*)(KV + rowbase + DM);
        float4 v0 = vsrc[0], v1 = vsrc[1];
        Vt[dd + 0][r] = v0.x; Vt[dd + 1][r] = v0.y;
        Vt[dd + 2][r] = v0.z; Vt[dd + 3][r] = v0.w;
        Vt[dd + 4][r] = v1.x; Vt[dd + 5][r] = v1.y;
        Vt[dd + 6][r] = v1.z; Vt[dd + 7][r] = v1.w;
        const float4* src1 = (const float4*)(Q + ((long)(b * Npt + q0 + r)) * DM + h * DH + dd + 4);
        *(float4*)&Ps[r][dd + 4] = src1[0];
    }
    __syncthreads();

    uint32_t aq[4][4];
#pragma unroll
    for (int ks = 0; ks < 4; ks++) {
        aq[ks][0] = __float_as_uint(Ps[mm + g][ks * 8 + c4]);
        aq[ks][1] = __float_as_uint(Ps[mm + 8 + g][ks * 8 + c4]);
        aq[ks][2] = __float_as_uint(Ps[mm + g][ks * 8 + c4 + 4]);
        aq[ks][3] = __float_as_uint(Ps[mm + 8 + g][ks * 8 + c4 + 4]);
    }
    float o_c[2][4] = {};
    float m0 = -1e30f, m1 = -1e30f, l0 = 0.f, l1 = 0.f;
    const float scale = 0.17677669529663687f;   // 1/sqrt(32)

    const int NT = Npt / 64;
    for (int kt = 0; kt < NT; kt++) {
        float kreg[8], vreg[8];
        {
            int ktn = (kt + 1 < NT) ? kt + 1 : kt;
            long rowbase = ((long)(b * Npt + ktn * 64 + r)) * (2 * DM) + h * DH + dd;
            const float4* ksrc = (const float4*)(KV + rowbase);
            *(float4*)&kreg[0] = ksrc[0];
            *(float4*)&kreg[4] = ksrc[1];
            const float4* vsrc = (const float4*)(KV + rowbase + DM);
            *(float4*)&vreg[0] = vsrc[0];
            *(float4*)&vreg[4] = vsrc[1];
        }
        float sc[4][4] = {};
#pragma unroll
        for (int ks = 0; ks < 4; ks++) {
#pragma unroll
            for (int nt = 0; nt < 4; nt++) {
                int n0 = nh * 32 + nt * 8;
                uint32_t bk[2];
                bk[0] = __float_as_uint(Ks[n0 + g][ks * 8 + c4]);
                bk[1] = __float_as_uint(Ks[n0 + g][ks * 8 + c4 + 4]);
                mma_tf32(sc[nt], aq[ks], bk);
            }
        }
#pragma unroll
        for (int nt = 0; nt < 4; nt++)
#pragma unroll
            for (int j = 0; j < 4; j++) sc[nt][j] *= scale;
        {
            float pmax0 = -1e30f, pmax1 = -1e30f;
#pragma unroll
            for (int nt = 0; nt < 4; nt++) {
                pmax0 = fmaxf(pmax0, fmaxf(sc[nt][0], sc[nt][1]));
                pmax1 = fmaxf(pmax1, fmaxf(sc[nt][2], sc[nt][3]));
            }
            pmax0 = fmaxf(pmax0, __shfl_xor_sync(0xffffffffu, pmax0, 1));
            pmax0 = fmaxf(pmax0, __shfl_xor_sync(0xffffffffu, pmax0, 2));
            pmax1 = fmaxf(pmax1, __shfl_xor_sync(0xffffffffu, pmax1, 1));
            pmax1 = fmaxf(pmax1, __shfl_xor_sync(0xffffffffu, pmax1, 2));
            if (c4 == 0) { pm[r0][nh] = pmax0; pm[r1][nh] = pmax1; }
        }
        __syncthreads();                     // bar A
        *(float4*)&Ks[r][dd]     = *(float4*)&kreg[0];
        *(float4*)&Ks[r][dd + 4] = *(float4*)&kreg[4];
        float corr0, corr1;
        {
            float mn0 = fmaxf(m0, fmaxf(pm[r0][0], pm[r0][1]));
            float mn1 = fmaxf(m1, fmaxf(pm[r1][0], pm[r1][1]));
            corr0 = __expf(m0 - mn0);
            corr1 = __expf(m1 - mn1);
            m0 = mn0; m1 = mn1;
            float ps0 = 0.f, ps1 = 0.f;
#pragma unroll
            for (int nt = 0; nt < 4; nt++) {
                sc[nt][0] = __expf(sc[nt][0] - mn0);
                sc[nt][1] = __expf(sc[nt][1] - mn0);
                sc[nt][2] = __expf(sc[nt][2] - mn1);
                sc[nt][3] = __expf(sc[nt][3] - mn1);
                ps0 += sc[nt][0] + sc[nt][1];
                ps1 += sc[nt][2] + sc[nt][3];
                int n0 = nh * 32 + nt * 8 + 2 * c4;
                *(float2*)&Ps[r0][n0] = make_float2(sc[nt][0], sc[nt][1]);
                *(float2*)&Ps[r1][n0] = make_float2(sc[nt][2], sc[nt][3]);
            }
            ps0 += __shfl_xor_sync(0xffffffffu, ps0, 1);
            ps0 += __shfl_xor_sync(0xffffffffu, ps0, 2);
            ps1 += __shfl_xor_sync(0xffffffffu, ps1, 1);
            ps1 += __shfl_xor_sync(0xffffffffu, ps1, 2);
            if (c4 == 0) { psum[r0][nh] = ps0; psum[r1][nh] = ps1; }
            o_c[0][0] *= corr0; o_c[0][1] *= corr0; o_c[1][0] *= corr0; o_c[1][1] *= corr0;
            o_c[0][2] *= corr1; o_c[0][3] *= corr1; o_c[1][2] *= corr1; o_c[1][3] *= corr1;
        }
        __syncthreads();                     // bar B
        l0 = l0 * corr0 + psum[r0][0] + psum[r0][1];
        l1 = l1 * corr1 + psum[r1][0] + psum[r1][1];
#pragma unroll
        for (int ks = 0; ks < 8; ks++) {
            uint32_t ap[4];
            ap[0] = __float_as_uint(Ps[mm + g][ks * 8 + c4]);
            ap[1] = __float_as_uint(Ps[mm + 8 + g][ks * 8 + c4]);
            ap[2] = __float_as_uint(Ps[mm + g][ks * 8 + c4 + 4]);
            ap[3] = __float_as_uint(Ps[mm + 8 + g][ks * 8 + c4 + 4]);
#pragma unroll
            for (int nt = 0; nt < 2; nt++) {
                int n0 = nh * 16 + nt * 8;
                uint32_t bv[2];
                bv[0] = __float_as_uint(Vt[n0 + g][ks * 8 + c4]);
                bv[1] = __float_as_uint(Vt[n0 + g][ks * 8 + c4 + 4]);
                mma_tf32(o_c[nt], ap, bv);
            }
        }
        __syncthreads();                     // bar C
        Vt[dd + 0][r] = vreg[0]; Vt[dd + 1][r] = vreg[1];
        Vt[dd + 2][r] = vreg[2]; Vt[dd + 3][r] = vreg[3];
        Vt[dd + 4][r] = vreg[4]; Vt[dd + 5][r] = vreg[5];
        Vt[dd + 6][r] = vreg[6]; Vt[dd + 7][r] = vreg[7];
    }
    float inv0 = 1.f / l0;
    float inv1 = 1.f / l1;
#pragma unroll
    for (int nt = 0; nt < 2; nt++) {
        int colg = h * DH + nh * 16 + nt * 8 + 2 * c4;
        float* dst0 = O + (long)(b * Npt + q0 + mm + g) * DM + colg;
        float* dst1 = O + (long)(b * Npt + q0 + mm + 8 + g) * DM + colg;
        *(float2*)dst0 = make_float2(o_c[nt][0] * inv0, o_c[nt][1] * inv0);
        *(float2*)dst1 = make_float2(o_c[nt][2] * inv1, o_c[nt][3] * inv1);
    }
}

// ---------------- layernorm + relu --------------------------------------------
__global__ void ln_relu(const float* __restrict__ g, const float* __restrict__ bta) {
    int warp = threadIdx.x >> 5, lane = threadIdx.x & 31;
    long row = (long)blockIdx.x * 8 + warp;
    float4 v = *(const float4*)&g_h[row * DM + lane * 4];
    float s = v.x + v.y + v.z + v.w;
#pragma unroll
    for (int o = 16; o; o >>= 1) s += __shfl_xor_sync(0xffffffffu, s, o);
    float mu = s * (1.f / 128.f);
    float d0 = v.x - mu, d1 = v.y - mu, d2 = v.z - mu, d3 = v.w - mu;
    float vs = d0 * d0 + d1 * d1 + d2 * d2 + d3 * d3;
#pragma unroll
    for (int o = 16; o; o >>= 1) vs += __shfl_xor_sync(0xffffffffu, vs, o);
    float inv = rsqrtf(vs * (1.f / 128.f) + 1e-5f);
    float4 gg = *(const float4*)&g[lane * 4];
    float4 bb = *(const float4*)&bta[lane * 4];
    float4 r;
    r.x = fmaxf(d0 * inv * gg.x + bb.x, 0.f);
    r.y = fmaxf(d1 * inv * gg.y + bb.y, 0.f);
    r.z = fmaxf(d2 * inv * gg.z + bb.z, 0.f);
    r.w = fmaxf(d3 * inv * gg.w + bb.w, 0.f);
    *(float4*)&g_h[row * DM + lane * 4] = r;
}

// ---------------- launch ------------------------------------------------------
extern "C" void kernel_launch(void* const* d_in, const int* in_sizes, int n_in,
                              void* d_out, int out_size) {
    const float* xyz_imu  = (const float*)d_in[0];
    const float* feat_pc  = (const float*)d_in[1];
    const float* img_feat = (const float*)d_in[2];
    const float* K_mat    = (const float*)d_in[3];
    const float* T_cam    = (const float*)d_in[4];
    const float* img_size = (const float*)d_in[5];
    const float* w_q   = (const float*)d_in[6];
    const float* b_q   = (const float*)d_in[7];
    const float* w_off = (const float*)d_in[8];
    const float* b_off = (const float*)d_in[9];
    const float* w_alpha = (const float*)d_in[10];
    const float* b_alpha = (const float*)d_in[11];
    const float* w_k   = (const float*)d_in[12];
    const float* b_k   = (const float*)d_in[13];
    const float* w_v   = (const float*)d_in[14];
    const float* b_v   = (const float*)d_in[15];
    const float* in_wq = (const float*)d_in[16];
    const float* in_wk = (const float*)d_in[17];
    const float* in_wv = (const float*)d_in[18];
    const float* in_bq = (const float*)d_in[19];
    const float* in_bk = (const float*)d_in[20];
    const float* in_bv = (const float*)d_in[21];
    const float* out_w = (const float*)d_in[22];
    const float* out_b = (const float*)d_in[23];
    const float* fw1   = (const float*)d_in[24];
    const float* fb1   = (const float*)d_in[25];
    const float* ln_g  = (const float*)d_in[26];
    const float* ln_b  = (const float*)d_in[27];
    const float* fw2   = (const float*)d_in[28];
    const float* fb2   = (const float*)d_in[29];
    float* out = (float*)d_out;

    void *pQp, *pFagg, *pq, *pkv, *po, *pconcat, *ph, *pwkv, *pbkv;
    cudaGetSymbolAddress(&pQp, g_Qp);
    cudaGetSymbolAddress(&pFagg, g_Fagg);
    cudaGetSymbolAddress(&pq, g_q);
    cudaGetSymbolAddress(&pkv, g_kv);
    cudaGetSymbolAddress(&po, g_o);
    cudaGetSymbolAddress(&pconcat, g_concat);
    cudaGetSymbolAddress(&ph, g_h);
    cudaGetSymbolAddress(&pwkv, g_wkv);
    cudaGetSymbolAddress(&pbkv, g_bkv);

    transpose_img<<<dim3(HW / 32, CI / 32, Bsz), dim3(32, 8)>>>(img_feat);
    fuse_weights<<<dim3(DM, 2), CI>>>(in_wk, w_k, b_k, in_bk, in_wv, w_v, b_v, in_bv);
    gemm128t<<<dim3(NPTS / 128, 2), 256>>>(feat_pc, w_q, b_q, (float*)pQp, 128, 128, 0);
    offlog_kernel<<<NPTS / 8, 256>>>(w_off, b_off, w_alpha, b_alpha);
    sampler_kernel<<<NPTS / 8, 256>>>(xyz_imu, feat_pc, K_mat, T_cam, img_size);
    gemm128t<<<dim3(NPTS / 128, 2), 256>>>((const float*)pQp, in_wq, in_bq, (float*)pq, 128, 128, 0);
    // fused k|v projection: C = Fagg @ [wkk;wvv]^T, ldc=256
    gemm128t<<<dim3(NPTS / 128, 4), 256>>>((const float*)pFagg, (const float*)pwkv,
                                           (const float*)pbkv, (float*)pkv, 256, 256, 0);
    flash_attn_mma<<<dim3(Npt / 64, Bsz * NH), 256>>>((const float*)pq, (const float*)pkv,
                                                      (float*)po);
    gemm128t<<<dim3(NPTS / 128, 2), 256>>>((const float*)po, out_w, out_b,
                                           (float*)pconcat, 128, 256, 128);
    gemm128t<<<dim3(NPTS / 128, 2), 256>>>((const float*)pconcat, fw1, fb1, (float*)ph, 256, 128, 0);
    ln_relu<<<NPTS / 8, 256>>>(ln_g, ln_b);
    gemm128t<<<dim3(NPTS / 128, 2), 256>>>((const float*)ph, fw2, fb2, out, 128, 128, 0);
}

// round 9
// speedup vs baseline: 1.1058x; 1.1058x over previous
#include <cuda_runtime.h>
#include <cuda_bf16.h>
#include <math.h>
#include <stdint.h>

// Problem constants
#define Bsz 2
#define Npt 4096
#define CP 128
#define CI 256
#define DM 128
#define NH 4
#define KS 8
#define HF 64
#define WF 128
#define DH 32
#define NPTS (Bsz*Npt)      // 8192
#define HW (HF*WF)          // 8192
#define QLD 192             // g_qol row stride

// ---------------- scratch (device globals; no allocation allowed) -------------
__device__ float g_img_t[Bsz*HW*CI];        // [B][HW][CI]
__device__ float g_qol[NPTS*QLD];           // cols 0-127: q, 128-151: off+logits
__device__ float g_Fagg[NPTS*CI];
__device__ float g_kv[NPTS*2*DM];           // [p][0:128]=k, [p][128:256]=v
__device__ float g_o[NPTS*DM];
__device__ float g_h[NPTS*DM];
__device__ float g_wkv[2*DM*CI];
__device__ float g_bkv[2*DM];
__device__ float g_wq2[QLD*DM];             // rows 0-127: in_wq@w_q; 128-151: [w_off;w_alpha]@w_q; 152-191: 0
__device__ float g_bq2[QLD];
__device__ float g_wo2[DM*DM];              // fw1[:,128:] @ out_w
__device__ float g_bh[DM];                  // fw1[:,128:] @ out_b + fb1

// ---------------- tf32 mma helper ---------------------------------------------
__device__ __forceinline__ void mma_tf32(float* d, const uint32_t* a, const uint32_t* b) {
    asm volatile(
        "mma.sync.aligned.m16n8k8.row.col.f32.tf32.tf32.f32 "
        "{%0,%1,%2,%3}, {%4,%5,%6,%7}, {%8,%9}, {%0,%1,%2,%3};\n"
        : "+f"(d[0]), "+f"(d[1]), "+f"(d[2]), "+f"(d[3])
        : "r"(a[0]), "r"(a[1]), "r"(a[2]), "r"(a[3]), "r"(b[0]), "r"(b[1]));
}

// ---------------- img_feat transpose ------------------------------------------
__global__ void transpose_img(const float* __restrict__ in) {
    __shared__ float tile[32][33];
    int b  = blockIdx.z;
    int hw0 = blockIdx.x * 32;
    int c0  = blockIdx.y * 32;
    int tx = threadIdx.x, ty = threadIdx.y;
#pragma unroll
    for (int i = 0; i < 4; i++) {
        int c = c0 + ty + i * 8;
        tile[ty + i * 8][tx] = in[((long)(b * CI + c)) * HW + hw0 + tx];
    }
    __syncthreads();
#pragma unroll
    for (int i = 0; i < 4; i++) {
        int hw = hw0 + ty + i * 8;
        g_img_t[((long)b * HW + hw) * CI + c0 + tx] = tile[tx][ty + i * 8];
    }
}

// ---------------- prep: all folded weights in one launch ----------------------
// grid (128, 5), 256 threads.
__global__ void prep_weights(
        const float* __restrict__ in_wk, const float* __restrict__ w_k,
        const float* __restrict__ b_k,   const float* __restrict__ in_bk,
        const float* __restrict__ in_wv, const float* __restrict__ w_v,
        const float* __restrict__ b_v,   const float* __restrict__ in_bv,
        const float* __restrict__ in_wq, const float* __restrict__ w_q,
        const float* __restrict__ b_q,   const float* __restrict__ in_bq,
        const float* __restrict__ w_off, const float* __restrict__ b_off,
        const float* __restrict__ w_alpha, const float* __restrict__ b_alpha,
        const float* __restrict__ fw1,   const float* __restrict__ out_w,
        const float* __restrict__ out_b, const float* __restrict__ fb1) {
    int i = blockIdx.x;
    int sel = blockIdx.y;
    int j = threadIdx.x;
    if (sel <= 1) {                       // wkv = in_w{k,v} @ w_{k,v}  (256 cols)
        const float* inw = sel ? in_wv : in_wk;
        const float* w   = sel ? w_v : w_k;
        float acc = 0.f;
#pragma unroll 8
        for (int d = 0; d < DM; d++) acc += inw[i * DM + d] * w[d * CI + j];
        g_wkv[(sel * DM + i) * CI + j] = acc;
        if (j == 0) {
            const float* bb  = sel ? b_v : b_k;
            const float* inb = sel ? in_bv : in_bk;
            float ba = 0.f;
            for (int d = 0; d < DM; d++) ba += inw[i * DM + d] * bb[d];
            g_bkv[sel * DM + i] = ba + inb[i];
        }
    } else if (sel == 2) {                // w_qq = in_wq @ w_q (128 cols)
        if (j < DM) {
            float acc = 0.f;
#pragma unroll 8
            for (int d = 0; d < DM; d++) acc += in_wq[i * DM + d] * w_q[d * DM + j];
            g_wq2[i * DM + j] = acc;
        }
        if (j == 0) {
            float ba = 0.f;
            for (int d = 0; d < DM; d++) ba += in_wq[i * DM + d] * b_q[d];
            g_bq2[i] = ba + in_bq[i];
        }
    } else if (sel == 3) {                // w_o2 = fw1[:,128:] @ out_w (128 cols)
        if (j < DM) {
            float acc = 0.f;
#pragma unroll 8
            for (int d = 0; d < DM; d++) acc += fw1[i * (CP + DM) + CP + d] * out_w[d * DM + j];
            g_wo2[i * DM + j] = acc;
        }
        if (j == 0) {
            float ba = 0.f;
            for (int d = 0; d < DM; d++) ba += fw1[i * (CP + DM) + CP + d] * out_b[d];
            g_bh[i] = ba + fb1[i];
        }
    } else {                              // w_ol = [w_off;w_alpha] @ w_q  rows 128..191
        if (i < 64) {
            if (j < DM) {
                float acc = 0.f;
                if (i < 24) {
                    const float* wr = (i < 16) ? (w_off + i * DM) : (w_alpha + (i - 16) * DM);
#pragma unroll 8
                    for (int d = 0; d < DM; d++) acc += wr[d] * w_q[d * DM + j];
                }
                g_wq2[(DM + i) * DM + j] = acc;
            }
            if (j == 0) {
                float ba = 0.f;
                if (i < 24) {
                    const float* wr = (i < 16) ? (w_off + i * DM) : (w_alpha + (i - 16) * DM);
                    for (int d = 0; d < DM; d++) ba += wr[d] * b_q[d];
                    ba += (i < 16) ? b_off[i] : b_alpha[i - 16];
                }
                g_bq2[DM + i] = ba;
            }
        }
    }
}

// ---------------- tf32 MMA GEMM: C = A @ W^T + bias, 64x64 tile ---------------
__global__ __launch_bounds__(256) void gemm64t(const float* __restrict__ A,
                                               const float* __restrict__ W,
                                               const float* __restrict__ bias,
                                               float* __restrict__ C,
                                               int K, int ldc, int c0) {
    __shared__ float As[64][36];
    __shared__ float Ws[64][36];
    int tid = threadIdx.x;
    int lane = tid & 31, w = tid >> 5;
    int m0b = blockIdx.x * 64, n0b = blockIdx.y * 64;
    int r = tid >> 2, dd = (tid & 3) * 8;
    int mm = (w & 3) * 16, nh = w >> 2;
    int g = lane >> 2, c4 = lane & 3;
    float acc[4][4] = {};
    for (int k0 = 0; k0 < K; k0 += 32) {
        const float4* as = (const float4*)&A[(long)(m0b + r) * K + k0 + dd];
        const float4* ws = (const float4*)&W[(long)(n0b + r) * K + k0 + dd];
        *(float4*)&As[r][dd]     = as[0];
        *(float4*)&As[r][dd + 4] = as[1];
        *(float4*)&Ws[r][dd]     = ws[0];
        *(float4*)&Ws[r][dd + 4] = ws[1];
        __syncthreads();
#pragma unroll
        for (int ks = 0; ks < 4; ks++) {
            uint32_t a[4];
            a[0] = __float_as_uint(As[mm + g][ks * 8 + c4]);
            a[1] = __float_as_uint(As[mm + 8 + g][ks * 8 + c4]);
            a[2] = __float_as_uint(As[mm + g][ks * 8 + c4 + 4]);
            a[3] = __float_as_uint(As[mm + 8 + g][ks * 8 + c4 + 4]);
#pragma unroll
            for (int nt = 0; nt < 4; nt++) {
                int n0 = nh * 32 + nt * 8;
                uint32_t b[2];
                b[0] = __float_as_uint(Ws[n0 + g][ks * 8 + c4]);
                b[1] = __float_as_uint(Ws[n0 + g][ks * 8 + c4 + 4]);
                mma_tf32(acc[nt], a, b);
            }
        }
        __syncthreads();
    }
#pragma unroll
    for (int nt = 0; nt < 4; nt++) {
        int n = n0b + nh * 32 + nt * 8 + 2 * c4;
        float b0 = bias[n], b1 = bias[n + 1];
        long row0 = m0b + mm + g, row1 = row0 + 8;
        *(float2*)&C[row0 * ldc + c0 + n] = make_float2(acc[nt][0] + b0, acc[nt][1] + b1);
        *(float2*)&C[row1 * ldc + c0 + n] = make_float2(acc[nt][2] + b0, acc[nt][3] + b1);
    }
}

// ---------------- dual-A GEMM: C = A1@W1a^T + A2@W2^T + bias ------------------
// W1 row stride 256 (uses first 128 cols); A1,A2,W2 row stride 128. N=128 tiles.
__global__ __launch_bounds__(256) void gemm_dual(const float* __restrict__ A1,
                                                 const float* __restrict__ W1,
                                                 const float* __restrict__ A2,
                                                 const float* __restrict__ W2,
                                                 const float* __restrict__ bias,
                                                 float* __restrict__ C) {
    __shared__ float As[64][36];
    __shared__ float Ws[64][36];
    int tid = threadIdx.x;
    int lane = tid & 31, w = tid >> 5;
    int m0b = blockIdx.x * 64, n0b = blockIdx.y * 64;
    int r = tid >> 2, dd = (tid & 3) * 8;
    int mm = (w & 3) * 16, nh = w >> 2;
    int g = lane >> 2, c4 = lane & 3;
    float acc[4][4] = {};
#pragma unroll
    for (int ph = 0; ph < 2; ph++) {
        const float* A = ph ? A2 : A1;
        const float* W = ph ? W2 : W1;
        int ldw = ph ? DM : (CP + DM);
        for (int k0 = 0; k0 < DM; k0 += 32) {
            const float4* as = (const float4*)&A[(long)(m0b + r) * DM + k0 + dd];
            const float4* ws = (const float4*)&W[(long)(n0b + r) * ldw + k0 + dd];
            *(float4*)&As[r][dd]     = as[0];
            *(float4*)&As[r][dd + 4] = as[1];
            *(float4*)&Ws[r][dd]     = ws[0];
            *(float4*)&Ws[r][dd + 4] = ws[1];
            __syncthreads();
#pragma unroll
            for (int ks = 0; ks < 4; ks++) {
                uint32_t a[4];
                a[0] = __float_as_uint(As[mm + g][ks * 8 + c4]);
                a[1] = __float_as_uint(As[mm + 8 + g][ks * 8 + c4]);
                a[2] = __float_as_uint(As[mm + g][ks * 8 + c4 + 4]);
                a[3] = __float_as_uint(As[mm + 8 + g][ks * 8 + c4 + 4]);
#pragma unroll
                for (int nt = 0; nt < 4; nt++) {
                    int n0 = nh * 32 + nt * 8;
                    uint32_t b[2];
                    b[0] = __float_as_uint(Ws[n0 + g][ks * 8 + c4]);
                    b[1] = __float_as_uint(Ws[n0 + g][ks * 8 + c4 + 4]);
                    mma_tf32(acc[nt], a, b);
                }
            }
            __syncthreads();
        }
    }
#pragma unroll
    for (int nt = 0; nt < 4; nt++) {
        int n = n0b + nh * 32 + nt * 8 + 2 * c4;
        float b0 = bias[n], b1 = bias[n + 1];
        long row0 = m0b + mm + g, row1 = row0 + 8;
        *(float2*)&C[row0 * DM + n] = make_float2(acc[nt][0] + b0, acc[nt][1] + b1);
        *(float2*)&C[row1 * DM + n] = make_float2(acc[nt][2] + b0, acc[nt][3] + b1);
    }
}

// ---------------- sampler: warp-per-point deformable gather -------------------
__global__ __launch_bounds__(256) void sampler_kernel(
        const float* __restrict__ xyz,
        const float* __restrict__ Km, const float* __restrict__ Tc,
        const float* __restrict__ img_size) {
    int tid = threadIdx.x;
    int lane = tid & 31, w = tid >> 5;
    long p = (long)blockIdx.x * 8 + w;
    int b = (int)(p >> 12);

    float ol = (lane < 24) ? g_qol[p * QLD + DM + lane] : 0.f;

    float lg = __shfl_sync(0xffffffffu, ol, 16 + (lane & 7));
    float mx = lg;
#pragma unroll
    for (int o = 1; o <= 4; o <<= 1) mx = fmaxf(mx, __shfl_xor_sync(0xffffffffu, mx, o));
    float ex = __expf(lg - mx);
    float se = ex;
#pragma unroll
    for (int o = 1; o <= 4; o <<= 1) se += __shfl_xor_sync(0xffffffffu, se, o);

    int k = lane >> 2, c = lane & 3;
    float al = __shfl_sync(0xffffffffu, ex, k) / se;
    float offu = __shfl_sync(0xffffffffu, ol, 2 * k);
    float offv = __shfl_sync(0xffffffffu, ol, 2 * k + 1);

    float X = xyz[p * 3], Y = xyz[p * 3 + 1], Z = xyz[p * 3 + 2];
    const float* T = Tc + b * 16;
    float Xc = T[0] * X + T[1] * Y + T[2]  * Z + T[3];
    float Yc = T[4] * X + T[5] * Y + T[6]  * Z + T[7];
    float Zc = T[8] * X + T[9] * Y + T[10] * Z + T[11];
    float Zf = -Zc;
    float Zs = (Zf > 1e-6f) ? Zf : 1e-6f;
    const float* Kc = Km + b * 9;
    float u = (Kc[0] * Xc + Kc[1] * Yc + Kc[2] * Zf) / Zs;
    float v = (Kc[3] * Xc + Kc[4] * Yc + Kc[5] * Zf) / Zs;
    float Hi = img_size[b * 2], Wi = img_size[b * 2 + 1];
    float Hfi = fmaxf(Hi / 8.f, 1.f), Wfi = fmaxf(Wi / 8.f, 1.f);
    float uf = u * (Wfi / Wi), vf = v * (Hfi / Hi);

    float us = uf + offu, vs = vf + offv;
    float xn = fminf(fmaxf(2.f * (us / 127.f) - 1.f, -1.5f), 1.5f);
    float yn = fminf(fmaxf(2.f * (vs / 63.f)  - 1.f, -1.5f), 1.5f);
    float ix = ((xn + 1.f) * (float)WF - 1.f) * 0.5f;
    float iy = ((yn + 1.f) * (float)HF - 1.f) * 0.5f;
    float x0f = floorf(ix), y0f = floorf(iy);
    float wx1 = ix - x0f, wx0 = 1.f - wx1;
    float wy1 = iy - y0f, wy0 = 1.f - wy1;
    float xc = x0f + (float)(c & 1);
    float yc = y0f + (float)(c >> 1);
    float wgt = ((c & 1) ? wx1 : wx0) * ((c >> 1) ? wy1 : wy0) * al;
    bool valid = (xc >= 0.f) && (xc < (float)WF) && (yc >= 0.f) && (yc < (float)HF);
    int xi = min(max((int)xc, 0), WF - 1);
    int yi = min(max((int)yc, 0), HF - 1);
    int sidx = yi * WF + xi;
    if (!valid) wgt = 0.f;

    float acc[8] = {};
    const float* imgb = g_img_t + (long)b * HW * CI + lane;
#pragma unroll
    for (int e = 0; e < 32; e++) {
        float we = __shfl_sync(0xffffffffu, wgt, e);
        int   ie = __shfl_sync(0xffffffffu, sidx, e);
        if (we != 0.f) {
            const float* basep = imgb + (long)ie * CI;
#pragma unroll
            for (int j = 0; j < 8; j++) acc[j] += we * basep[j * 32];
        }
    }
#pragma unroll
    for (int j = 0; j < 8; j++) g_Fagg[p * CI + j * 32 + lane] = acc[j];
}

// ---------------- flash attention v2: BQ=64, static smem ----------------------
// Q from g_qol (row stride QLD=192, cols 0-127).
__global__ __launch_bounds__(256) void flash_attn_mma(const float* __restrict__ Q,
                                                      const float* __restrict__ KV,
                                                      float* __restrict__ O) {
    __shared__ float Ks[64][36];
    __shared__ float Vt[32][68];
    __shared__ float Ps[64][68];
    __shared__ float pm[64][2];
    __shared__ float psum[64][2];

    int tid = threadIdx.x;
    int lane = tid & 31, w = tid >> 5;
    int bh = blockIdx.y;
    int b = bh >> 2, h = bh & 3;
    int q0 = blockIdx.x * 64;

    int r = tid >> 2, dd = (tid & 3) * 8;
    int mm = (w & 3) * 16, nh = w >> 2;
    int g = lane >> 2, c4 = lane & 3;
    int r0 = mm + g, r1 = mm + 8 + g;

    {
        const float4* src = (const float4*)(Q + ((long)(b * Npt + q0 + r)) * QLD + h * DH + dd);
        *(float4*)&Ps[r][dd]     = src[0];
        long rowbase = ((long)(b * Npt + r)) * (2 * DM) + h * DH + dd;
        const float4* ksrc = (const float4*)(KV + rowbase);
        *(float4*)&Ks[r][dd]     = ksrc[0];
        *(float4*)&Ks[r][dd + 4] = ksrc[1];
        const float4* vsrc = (const float4*)(KV + rowbase + DM);
        float4 v0 = vsrc[0], v1 = vsrc[1];
        Vt[dd + 0][r] = v0.x; Vt[dd + 1][r] = v0.y;
        Vt[dd + 2][r] = v0.z; Vt[dd + 3][r] = v0.w;
        Vt[dd + 4][r] = v1.x; Vt[dd + 5][r] = v1.y;
        Vt[dd + 6][r] = v1.z; Vt[dd + 7][r] = v1.w;
        *(float4*)&Ps[r][dd + 4] = src[1];
    }
    __syncthreads();

    uint32_t aq[4][4];
#pragma unroll
    for (int ks = 0; ks < 4; ks++) {
        aq[ks][0] = __float_as_uint(Ps[mm + g][ks * 8 + c4]);
        aq[ks][1] = __float_as_uint(Ps[mm + 8 + g][ks * 8 + c4]);
        aq[ks][2] = __float_as_uint(Ps[mm + g][ks * 8 + c4 + 4]);
        aq[ks][3] = __float_as_uint(Ps[mm + 8 + g][ks * 8 + c4 + 4]);
    }
    float o_c[2][4] = {};
    float m0 = -1e30f, m1 = -1e30f, l0 = 0.f, l1 = 0.f;
    const float scale = 0.17677669529663687f;

    const int NT = Npt / 64;
    for (int kt = 0; kt < NT; kt++) {
        float kreg[8], vreg[8];
        {
            int ktn = (kt + 1 < NT) ? kt + 1 : kt;
            long rowbase = ((long)(b * Npt + ktn * 64 + r)) * (2 * DM) + h * DH + dd;
            const float4* ksrc = (const float4*)(KV + rowbase);
            *(float4*)&kreg[0] = ksrc[0];
            *(float4*)&kreg[4] = ksrc[1];
            const float4* vsrc = (const float4*)(KV + rowbase + DM);
            *(float4*)&vreg[0] = vsrc[0];
            *(float4*)&vreg[4] = vsrc[1];
        }
        float sc[4][4] = {};
#pragma unroll
        for (int ks = 0; ks < 4; ks++) {
#pragma unroll
            for (int nt = 0; nt < 4; nt++) {
                int n0 = nh * 32 + nt * 8;
                uint32_t bk[2];
                bk[0] = __float_as_uint(Ks[n0 + g][ks * 8 + c4]);
                bk[1] = __float_as_uint(Ks[n0 + g][ks * 8 + c4 + 4]);
                mma_tf32(sc[nt], aq[ks], bk);
            }
        }
#pragma unroll
        for (int nt = 0; nt < 4; nt++)
#pragma unroll
            for (int j = 0; j < 4; j++) sc[nt][j] *= scale;
        {
            float pmax0 = -1e30f, pmax1 = -1e30f;
#pragma unroll
            for (int nt = 0; nt < 4; nt++) {
                pmax0 = fmaxf(pmax0, fmaxf(sc[nt][0], sc[nt][1]));
                pmax1 = fmaxf(pmax1, fmaxf(sc[nt][2], sc[nt][3]));
            }
            pmax0 = fmaxf(pmax0, __shfl_xor_sync(0xffffffffu, pmax0, 1));
            pmax0 = fmaxf(pmax0, __shfl_xor_sync(0xffffffffu, pmax0, 2));
            pmax1 = fmaxf(pmax1, __shfl_xor_sync(0xffffffffu, pmax1, 1));
            pmax1 = fmaxf(pmax1, __shfl_xor_sync(0xffffffffu, pmax1, 2));
            if (c4 == 0) { pm[r0][nh] = pmax0; pm[r1][nh] = pmax1; }
        }
        __syncthreads();                     // bar A
        *(float4*)&Ks[r][dd]     = *(float4*)&kreg[0];
        *(float4*)&Ks[r][dd + 4] = *(float4*)&kreg[4];
        float corr0, corr1;
        {
            float mn0 = fmaxf(m0, fmaxf(pm[r0][0], pm[r0][1]));
            float mn1 = fmaxf(m1, fmaxf(pm[r1][0], pm[r1][1]));
            corr0 = __expf(m0 - mn0);
            corr1 = __expf(m1 - mn1);
            m0 = mn0; m1 = mn1;
            float ps0 = 0.f, ps1 = 0.f;
#pragma unroll
            for (int nt = 0; nt < 4; nt++) {
                sc[nt][0] = __expf(sc[nt][0] - mn0);
                sc[nt][1] = __expf(sc[nt][1] - mn0);
                sc[nt][2] = __expf(sc[nt][2] - mn1);
                sc[nt][3] = __expf(sc[nt][3] - mn1);
                ps0 += sc[nt][0] + sc[nt][1];
                ps1 += sc[nt][2] + sc[nt][3];
                int n0 = nh * 32 + nt * 8 + 2 * c4;
                *(float2*)&Ps[r0][n0] = make_float2(sc[nt][0], sc[nt][1]);
                *(float2*)&Ps[r1][n0] = make_float2(sc[nt][2], sc[nt][3]);
            }
            ps0 += __shfl_xor_sync(0xffffffffu, ps0, 1);
            ps0 += __shfl_xor_sync(0xffffffffu, ps0, 2);
            ps1 += __shfl_xor_sync(0xffffffffu, ps1, 1);
            ps1 += __shfl_xor_sync(0xffffffffu, ps1, 2);
            if (c4 == 0) { psum[r0][nh] = ps0; psum[r1][nh] = ps1; }
            o_c[0][0] *= corr0; o_c[0][1] *= corr0; o_c[1][0] *= corr0; o_c[1][1] *= corr0;
            o_c[0][2] *= corr1; o_c[0][3] *= corr1; o_c[1][2] *= corr1; o_c[1][3] *= corr1;
        }
        __syncthreads();                     // bar B
        l0 = l0 * corr0 + psum[r0][0] + psum[r0][1];
        l1 = l1 * corr1 + psum[r1][0] + psum[r1][1];
#pragma unroll
        for (int ks = 0; ks < 8; ks++) {
            uint32_t ap[4];
            ap[0] = __float_as_uint(Ps[mm + g][ks * 8 + c4]);
            ap[1] = __float_as_uint(Ps[mm + 8 + g][ks * 8 + c4]);
            ap[2] = __float_as_uint(Ps[mm + g][ks * 8 + c4 + 4]);
            ap[3] = __float_as_uint(Ps[mm + 8 + g][ks * 8 + c4 + 4]);
#pragma unroll
            for (int nt = 0; nt < 2; nt++) {
                int n0 = nh * 16 + nt * 8;
                uint32_t bv[2];
                bv[0] = __float_as_uint(Vt[n0 + g][ks * 8 + c4]);
                bv[1] = __float_as_uint(Vt[n0 + g][ks * 8 + c4 + 4]);
                mma_tf32(o_c[nt], ap, bv);
            }
        }
        __syncthreads();                     // bar C
        Vt[dd + 0][r] = vreg[0]; Vt[dd + 1][r] = vreg[1];
        Vt[dd + 2][r] = vreg[2]; Vt[dd + 3][r] = vreg[3];
        Vt[dd + 4][r] = vreg[4]; Vt[dd + 5][r] = vreg[5];
        Vt[dd + 6][r] = vreg[6]; Vt[dd + 7][r] = vreg[7];
    }
    float inv0 = 1.f / l0;
    float inv1 = 1.f / l1;
#pragma unroll
    for (int nt = 0; nt < 2; nt++) {
        int colg = h * DH + nh * 16 + nt * 8 + 2 * c4;
        float* dst0 = O + (long)(b * Npt + q0 + mm + g) * DM + colg;
        float* dst1 = O + (long)(b * Npt + q0 + mm + 8 + g) * DM + colg;
        *(float2*)dst0 = make_float2(o_c[nt][0] * inv0, o_c[nt][1] * inv0);
        *(float2*)dst1 = make_float2(o_c[nt][2] * inv1, o_c[nt][3] * inv1);
    }
}

// ---------------- layernorm + relu --------------------------------------------
__global__ void ln_relu(const float* __restrict__ g, const float* __restrict__ bta) {
    int warp = threadIdx.x >> 5, lane = threadIdx.x & 31;
    long row = (long)blockIdx.x * 8 + warp;
    float4 v = *(const float4*)&g_h[row * DM + lane * 4];
    float s = v.x + v.y + v.z + v.w;
#pragma unroll
    for (int o = 16; o; o >>= 1) s += __shfl_xor_sync(0xffffffffu, s, o);
    float mu = s * (1.f / 128.f);
    float d0 = v.x - mu, d1 = v.y - mu, d2 = v.z - mu, d3 = v.w - mu;
    float vs = d0 * d0 + d1 * d1 + d2 * d2 + d3 * d3;
#pragma unroll
    for (int o = 16; o; o >>= 1) vs += __shfl_xor_sync(0xffffffffu, vs, o);
    float inv = rsqrtf(vs * (1.f / 128.f) + 1e-5f);
    float4 gg = *(const float4*)&g[lane * 4];
    float4 bb = *(const float4*)&bta[lane * 4];
    float4 r;
    r.x = fmaxf(d0 * inv * gg.x + bb.x, 0.f);
    r.y = fmaxf(d1 * inv * gg.y + bb.y, 0.f);
    r.z = fmaxf(d2 * inv * gg.z + bb.z, 0.f);
    r.w = fmaxf(d3 * inv * gg.w + bb.w, 0.f);
    *(float4*)&g_h[row * DM + lane * 4] = r;
}

// ---------------- launch ------------------------------------------------------
extern "C" void kernel_launch(void* const* d_in, const int* in_sizes, int n_in,
                              void* d_out, int out_size) {
    const float* xyz_imu  = (const float*)d_in[0];
    const float* feat_pc  = (const float*)d_in[1];
    const float* img_feat = (const float*)d_in[2];
    const float* K_mat    = (const float*)d_in[3];
    const float* T_cam    = (const float*)d_in[4];
    const float* img_size = (const float*)d_in[5];
    const float* w_q   = (const float*)d_in[6];
    const float* b_q   = (const float*)d_in[7];
    const float* w_off = (const float*)d_in[8];
    const float* b_off = (const float*)d_in[9];
    const float* w_alpha = (const float*)d_in[10];
    const float* b_alpha = (const float*)d_in[11];
    const float* w_k   = (const float*)d_in[12];
    const float* b_k   = (const float*)d_in[13];
    const float* w_v   = (const float*)d_in[14];
    const float* b_v   = (const float*)d_in[15];
    const float* in_wq = (const float*)d_in[16];
    const float* in_wk = (const float*)d_in[17];
    const float* in_wv = (const float*)d_in[18];
    const float* in_bq = (const float*)d_in[19];
    const float* in_bk = (const float*)d_in[20];
    const float* in_bv = (const float*)d_in[21];
    const float* out_w = (const float*)d_in[22];
    const float* out_b = (const float*)d_in[23];
    const float* fw1   = (const float*)d_in[24];
    const float* fb1   = (const float*)d_in[25];
    const float* ln_g  = (const float*)d_in[26];
    const float* ln_b  = (const float*)d_in[27];
    const float* fw2   = (const float*)d_in[28];
    const float* fb2   = (const float*)d_in[29];
    float* out = (float*)d_out;

    void *pqol, *pFagg, *pkv, *po, *ph, *pwkv, *pbkv, *pwq2, *pbq2, *pwo2, *pbh;
    cudaGetSymbolAddress(&pqol, g_qol);
    cudaGetSymbolAddress(&pFagg, g_Fagg);
    cudaGetSymbolAddress(&pkv, g_kv);
    cudaGetSymbolAddress(&po, g_o);
    cudaGetSymbolAddress(&ph, g_h);
    cudaGetSymbolAddress(&pwkv, g_wkv);
    cudaGetSymbolAddress(&pbkv, g_bkv);
    cudaGetSymbolAddress(&pwq2, g_wq2);
    cudaGetSymbolAddress(&pbq2, g_bq2);
    cudaGetSymbolAddress(&pwo2, g_wo2);
    cudaGetSymbolAddress(&pbh, g_bh);

    transpose_img<<<dim3(HW / 32, CI / 32, Bsz), dim3(32, 8)>>>(img_feat);
    prep_weights<<<dim3(DM, 5), 256>>>(in_wk, w_k, b_k, in_bk, in_wv, w_v, b_v, in_bv,
                                       in_wq, w_q, b_q, in_bq, w_off, b_off, w_alpha, b_alpha,
                                       fw1, out_w, out_b, fb1);
    // [q | offlog] = feat_pc @ g_wq2^T + g_bq2 : M=8192, N=192, K=128
    gemm64t<<<dim3(NPTS / 64, 3), 256>>>(feat_pc, (const float*)pwq2, (const float*)pbq2,
                                         (float*)pqol, 128, QLD, 0);
    sampler_kernel<<<NPTS / 8, 256>>>(xyz_imu, K_mat, T_cam, img_size);
    // [k | v] = Fagg @ g_wkv^T + g_bkv : N=256, K=256
    gemm64t<<<dim3(NPTS / 64, 4), 256>>>((const float*)pFagg, (const float*)pwkv,
                                         (const float*)pbkv, (float*)pkv, 256, 256, 0);
    flash_attn_mma<<<dim3(Npt / 64, Bsz * NH), 256>>>((const float*)pqol, (const float*)pkv,
                                                      (float*)po);
    // h = feat_pc @ fw1[:, :128]^T + o @ g_wo2^T + g_bh
    gemm_dual<<<dim3(NPTS / 64, 2), 256>>>(feat_pc, fw1, (const float*)po,
                                           (const float*)pwo2, (const float*)pbh, (float*)ph);
    ln_relu<<<NPTS / 8, 256>>>(ln_g, ln_b);
    gemm64t<<<dim3(NPTS / 64, 2), 256>>>((const float*)ph, fw2, fb2, out, 128, 128, 0);
}